// round 5
// baseline (speedup 1.0000x reference)
#include <cuda_runtime.h>
#include <math.h>

// Problem constants
#define BGR   128
#define N0    1024
#define NTOT  131072
#define ETOT  2097152
#define EPG   16384
#define DD    64
#define K1    820
#define K2    656
#define K3    525

#define NEG_INF __int_as_float(0xff800000)

// ---------------- scratch ---------------------------------------------------
__device__ float g_x[NTOT * DD];      // layer-3 input features
__device__ float g_y[NTOT * DD];      // sage output (layers 2,3)
__device__ float g_msg[NTOT * DD];    // layer-3 messages
__device__ float g_aggr[NTOT * DD];
__device__ float g_score[NTOT];
__device__ int   g_selold[NTOT];
__device__ float g_selscale[NTOT];
__device__ int   g_inv[NTOT];
__device__ float g_h[BGR * 2 * DD];
// compacted edge lists
__device__ unsigned long long g_comp1[ETOT];
__device__ unsigned long long g_comp2[ETOT];
__device__ int   g_ecnt[2];
// CSR scratch (layer 3)
__device__ int   g_deg[NTOT];
__device__ int   g_headp[NTOT];
__device__ int   g_cur[NTOT];
__device__ int   g_csr[ETOT];
// combo / LUT scratch (layers 1-2)
__device__ int   g_mask1[NTOT];
__device__ int   g_combo2[NTOT];
__device__ unsigned long long g_pres2[NTOT];
__device__ float g_sc1lut[64];
__device__ float g_x2lut[64 * 64];
__device__ float g_msg2lut[64 * 64];
__device__ float g_x2part[64 * 64];

// ---------------- helpers ----------------------------------------------------

__device__ __forceinline__ unsigned long long packkey(float s, int idx) {
    unsigned u = __float_as_uint(s);
    u = (u & 0x80000000u) ? ~u : (u | 0x80000000u);   // monotone-increasing map
    unsigned hi = ~u;                                 // ascending hi = descending score
    return ((unsigned long long)hi << 32) | (unsigned)idx;
}

// ascending bitonic sort of 1024 register-resident u64 keys (one per thread)
__device__ __forceinline__ void bitonic1024(unsigned long long& key,
                                            unsigned long long* sk, int t) {
    for (int ksz = 2; ksz <= 1024; ksz <<= 1) {
        for (int j = ksz >> 1; j >= 32; j >>= 1) {
            sk[t] = key;
            __syncthreads();
            unsigned long long o = sk[t ^ j];
            bool keepmin = (((t & j) == 0) == ((t & ksz) == 0));
            key = (keepmin == (o < key)) ? o : key;
            __syncthreads();
        }
        int jmax = ((ksz >> 1) < 16) ? (ksz >> 1) : 16;
        for (int j = jmax; j >= 1; j >>= 1) {
            unsigned long long o = __shfl_xor_sync(0xffffffffu, key, j);
            bool keepmin = (((t & j) == 0) == ((t & ksz) == 0));
            key = (keepmin == (o < key)) ? o : key;
        }
    }
}

// ---------------- init --------------------------------------------------------

__global__ void k_zero_init() {
    int i = blockIdx.x * blockDim.x + threadIdx.x;
    if (i < NTOT) { g_mask1[i] = 0; g_deg[i] = 0; }
    if (i < BGR * 2 * DD) g_h[i] = 0.f;
    if (i < 2) g_ecnt[i] = 0;
}

// ---------------- layer-1/2 LUT machinery --------------------------------------

__global__ void k_mask1(const int* __restrict__ src,
                        const int* __restrict__ dst,
                        const int* __restrict__ x_ids) {
    int e = blockIdx.x * blockDim.x + threadIdx.x;
    if (e >= ETOT) return;
    atomicOr(&g_mask1[dst[e]], 1 << x_ids[src[e]]);
}

__global__ void __launch_bounds__(512)
k_lutA(const float* __restrict__ emb,
       const float* __restrict__ W1, const float* __restrict__ b1,
       const float* __restrict__ U1, const float* __restrict__ p1) {
    __shared__ float s_emb[4][64], s_m1[4][64], s_amax[16][64], s_y1[64][64];
    __shared__ float s_scale[64];
    __shared__ float s_pinv;
    int t = threadIdx.x;
    if (t < 256) s_emb[t >> 6][t & 63] = emb[t];
    if (t == 0) {
        float s = 0.f;
        for (int i = 0; i < 64; i++) s += p1[i] * p1[i];
        s_pinv = 1.0f / sqrtf(s);
    }
    __syncthreads();
    if (t < 256) {
        int id = t >> 6, o = t & 63;
        float a = b1[o];
        for (int i = 0; i < 64; i++) a = fmaf(s_emb[id][i], W1[o * 64 + i], a);
        s_m1[id][o] = a > 0.f ? a : 0.f;
    }
    __syncthreads();
    for (int u = t; u < 16 * 64; u += 512) {
        int mask = u >> 6, o = u & 63;
        float v = NEG_INF;
        for (int id = 0; id < 4; id++)
            if ((mask >> id) & 1) v = fmaxf(v, s_m1[id][o]);
        if (mask == 0) v = 0.f;
        s_amax[mask][o] = v;
    }
    __syncthreads();
    for (int u = t; u < 64 * 64; u += 512) {
        int c = u >> 6, o = u & 63;
        int id = c >> 4, mask = c & 15;
        float a = 0.f;
        for (int i = 0; i < 64; i++) a = fmaf(s_amax[mask][i], U1[o * 128 + i], a);
        for (int i = 0; i < 64; i++) a = fmaf(s_emb[id][i], U1[o * 128 + 64 + i], a);
        s_y1[c][o] = a > 0.f ? a : 0.f;
    }
    __syncthreads();
    if (t < 64) {
        float s = 0.f;
        for (int i = 0; i < 64; i++) s = fmaf(s_y1[t][i], p1[i], s);
        s *= s_pinv;
        g_sc1lut[t] = s;
        s_scale[t]  = tanhf(s);
    }
    __syncthreads();
    for (int u = t; u < 64 * 64; u += 512) {
        int c = u >> 6, d = u & 63;
        g_x2lut[u] = s_y1[c][d] * s_scale[c];
    }
}

// msg2 rows + x-part of layer-2 concat GEMM (parallel, depends on g_x2lut)
__global__ void __launch_bounds__(512)
k_lutB(const float* __restrict__ W2, const float* __restrict__ b2,
       const float* __restrict__ U2) {
    int u = blockIdx.x * 512 + threadIdx.x;   // 0..4095
    int c = u >> 6, o = u & 63;
    const float* xr = g_x2lut + c * 64;
    float a = b2[o], x = 0.f;
    for (int i = 0; i < 64; i++) {
        float xv = xr[i];
        a = fmaf(xv, W2[o * 64 + i], a);
        x = fmaf(xv, U2[o * 128 + 64 + i], x);
    }
    g_msg2lut[u] = a > 0.f ? a : 0.f;
    g_x2part[u]  = x;
}

// ---------------- topk kernels --------------------------------------------------

// layer-1 topk: fused combo+score computation, seeds layer-2 combo/presence
__global__ void __launch_bounds__(1024)
k_topk1(const int* __restrict__ x_ids) {
    __shared__ unsigned long long sk[1024];
    __shared__ unsigned char scb[1024];
    int b = blockIdx.x, t = threadIdx.x;
    int node = b * 1024 + t;
    int id = x_ids[node];
    int c = id * 16 + (g_mask1[node] | (1 << id));
    scb[t] = (unsigned char)c;
    unsigned long long key = packkey(g_sc1lut[c], t);
    g_inv[node] = -1;
    __syncthreads();
    bitonic1024(key, sk, t);
    if (t < K1) {
        int idx = (int)(key & 0xffffffffu);
        int old = b * 1024 + idx;
        int nw  = b * K1 + t;
        g_inv[old]    = nw;
        int cc = scb[idx];
        g_combo2[nw]  = cc;
        g_pres2[nw]   = 1ull << cc;
    }
}

// generic topk over g_score
__global__ void __launch_bounds__(1024)
k_topk(int n_per, int k, int write_inv) {
    __shared__ unsigned long long sk[1024];
    int b = blockIdx.x, t = threadIdx.x;
    unsigned long long key = 0xFFFFFFFFFFFFFFFFull;
    if (t < n_per) {
        key = packkey(g_score[b * n_per + t], t);
        if (write_inv) g_inv[b * n_per + t] = -1;
    }
    __syncthreads();
    bitonic1024(key, sk, t);
    if (t < k) {
        int idx = (int)(key & 0xffffffffu);
        int old = b * n_per + idx;
        int nw  = b * k + t;
        g_selold[nw]   = old;
        g_selscale[nw] = tanhf(g_score[old]);
        if (write_inv) g_inv[old] = nw;
    }
}

// ---------------- edge passes -----------------------------------------------

// remap raw edges -> compacted comp1, fused layer-2 presence OR
__global__ void k_remap1(const int* __restrict__ src,
                         const int* __restrict__ dst) {
    int e = blockIdx.x * blockDim.x + threadIdx.x;   // exact coverage of ETOT
    int ns = g_inv[src[e]];
    int nd = g_inv[dst[e]];
    bool valid = (ns >= 0) && (nd >= 0);
    unsigned bal = __ballot_sync(0xffffffffu, valid);
    if (bal) {
        int lane = threadIdx.x & 31;
        int leader = __ffs(bal) - 1;
        int base = 0;
        if (lane == leader) base = atomicAdd(&g_ecnt[0], __popc(bal));
        base = __shfl_sync(0xffffffffu, base, leader);
        if (valid) {
            int pos = base + __popc(bal & ((1u << lane) - 1));
            g_comp1[pos] = ((unsigned long long)(unsigned)ns << 32) | (unsigned)nd;
            atomicOr(&g_pres2[nd], 1ull << g_combo2[ns]);
        }
    }
}

// remap comp1 -> comp2 (layer-3 edges), fused degree count
__global__ void k_remap2() {
    int i = blockIdx.x * blockDim.x + threadIdx.x;
    int total = g_ecnt[0];
    bool inr = i < total;
    int ns = -1, nd = -1;
    if (inr) {
        unsigned long long pr = g_comp1[i];
        ns = g_inv[(int)(pr >> 32)];
        nd = g_inv[(int)(pr & 0xffffffffu)];
    }
    bool valid = inr && ns >= 0 && nd >= 0;
    unsigned bal = __ballot_sync(0xffffffffu, valid);
    if (bal) {
        int lane = threadIdx.x & 31;
        int leader = __ffs(bal) - 1;
        int base = 0;
        if (lane == leader) base = atomicAdd(&g_ecnt[1], __popc(bal));
        base = __shfl_sync(0xffffffffu, base, leader);
        if (valid) {
            int pos = base + __popc(bal & ((1u << lane) - 1));
            g_comp2[pos] = ((unsigned long long)(unsigned)ns << 32) | (unsigned)nd;
            atomicAdd(&g_deg[nd], 1);
        }
    }
}

__global__ void __launch_bounds__(1024)
k_scan(int n_per) {
    __shared__ int s[1024];
    int g = blockIdx.x, t = threadIdx.x;
    int v = (t < n_per) ? g_deg[g * n_per + t] : 0;
    s[t] = v;
    __syncthreads();
    for (int off = 1; off < 1024; off <<= 1) {
        int u = (t >= off) ? s[t - off] : 0;
        __syncthreads();
        s[t] += u;
        __syncthreads();
    }
    if (t < n_per) {
        int h = g * EPG + (s[t] - v);
        g_headp[g * n_per + t] = h;
        g_cur[g * n_per + t]   = h;
    }
}

__global__ void k_fill() {
    int i = blockIdx.x * blockDim.x + threadIdx.x;
    if (i >= g_ecnt[1]) return;
    unsigned long long pr = g_comp2[i];
    int s = (int)(pr >> 32), d = (int)(pr & 0xffffffffu);
    int pos = atomicAdd(&g_cur[d], 1);
    g_csr[pos] = s;      // global layer-3 node index
}

// ---------------- aggregation ---------------------------------------------------

// layer-2: max over present msg2 LUT rows (L1-hot 16KB table)
__global__ void k_aggr2(int n) {
    int w = (blockIdx.x * blockDim.x + threadIdx.x) >> 5;
    int lane = threadIdx.x & 31;
    if (w >= n) return;
    unsigned long long m = g_pres2[w];
    float m0 = NEG_INF, m1 = NEG_INF;
    while (m) {
        int c = __ffsll(m) - 1;
        m &= m - 1;
        const float* r = g_msg2lut + c * 64;
        m0 = fmaxf(m0, __ldg(r + lane));
        m1 = fmaxf(m1, __ldg(r + lane + 32));
    }
    float* ar = g_aggr + (size_t)w * DD;
    ar[lane]      = m0;
    ar[lane + 32] = m1;
}

// layer-3: CSR gather-max with self-loop init
__global__ void k_aggr3(int n) {
    int w = (blockIdx.x * blockDim.x + threadIdx.x) >> 5;
    int lane = threadIdx.x & 31;
    if (w >= n) return;
    const float* mrow = g_msg + (size_t)w * DD;
    float m0 = mrow[lane];
    float m1 = mrow[lane + 32];
    int e   = g_headp[w];
    int end = g_cur[w];
    for (; e + 4 <= end; e += 4) {
        int s0 = __ldg(&g_csr[e]);
        int s1 = __ldg(&g_csr[e + 1]);
        int s2 = __ldg(&g_csr[e + 2]);
        int s3 = __ldg(&g_csr[e + 3]);
        const float* r0 = g_msg + (size_t)s0 * DD;
        const float* r1 = g_msg + (size_t)s1 * DD;
        const float* r2 = g_msg + (size_t)s2 * DD;
        const float* r3 = g_msg + (size_t)s3 * DD;
        float a0 = r0[lane], b0 = r0[lane + 32];
        float a1 = r1[lane], b1 = r1[lane + 32];
        float a2 = r2[lane], b2 = r2[lane + 32];
        float a3 = r3[lane], b3 = r3[lane + 32];
        m0 = fmaxf(fmaxf(fmaxf(m0, a0), fmaxf(a1, a2)), a3);
        m1 = fmaxf(fmaxf(fmaxf(m1, b0), fmaxf(b1, b2)), b3);
    }
    for (; e < end; e++) {
        int s0 = __ldg(&g_csr[e]);
        const float* r0 = g_msg + (size_t)s0 * DD;
        m0 = fmaxf(m0, r0[lane]);
        m1 = fmaxf(m1, r0[lane + 32]);
    }
    float* ar = g_aggr + (size_t)w * DD;
    ar[lane]      = m0;
    ar[lane + 32] = m1;
}

// ---------------- GEMMs ----------------------------------------------------------

__global__ void __launch_bounds__(128)
k_gemm64(const float* __restrict__ W, const float* __restrict__ bias, int n) {
    __shared__ float Wt[64][64];
    for (int t = threadIdx.x; t < 64 * 64; t += blockDim.x) {
        int o = t >> 6, i = t & 63;
        Wt[i][o] = W[t];
    }
    __syncthreads();
    int row = blockIdx.x * blockDim.x + threadIdx.x;
    if (row >= n) return;
    const float* xr = g_x + (size_t)row * DD;
    float acc[64];
#pragma unroll
    for (int o = 0; o < 64; o++) acc[o] = bias[o];
#pragma unroll 8
    for (int i = 0; i < 64; i++) {
        float xv = xr[i];
#pragma unroll
        for (int o = 0; o < 64; o++) acc[o] = fmaf(xv, Wt[i][o], acc[o]);
    }
    float* m = g_msg + (size_t)row * DD;
#pragma unroll
    for (int o = 0; o < 64; o++) m[o] = acc[o] > 0.f ? acc[o] : 0.f;
}

// layer-2: y = relu(aggr @ Ua^T + x2part[combo]); fused score
__global__ void __launch_bounds__(128)
k_gemmcat2(const float* __restrict__ U, const float* __restrict__ p, int n) {
    __shared__ float Ut[64][64];
    __shared__ float x2p[64][65];
    __shared__ float ps[64];
    __shared__ float pinv;
    for (int t = threadIdx.x; t < 64 * 64; t += blockDim.x) {
        int o = t >> 6, i = t & 63;
        Ut[i][o]            = U[o * 128 + i];
        x2p[t >> 6][t & 63] = g_x2part[t];
    }
    if (threadIdx.x < 64) ps[threadIdx.x] = p[threadIdx.x];
    __syncthreads();
    if (threadIdx.x == 0) {
        float s = 0.f;
        for (int i = 0; i < 64; i++) s += ps[i] * ps[i];
        pinv = 1.0f / sqrtf(s);
    }
    __syncthreads();
    int row = blockIdx.x * blockDim.x + threadIdx.x;
    if (row >= n) return;
    int c = g_combo2[row];
    const float* ar = g_aggr + (size_t)row * DD;
    float acc[64];
#pragma unroll
    for (int o = 0; o < 64; o++) acc[o] = x2p[c][o];
#pragma unroll 4
    for (int i = 0; i < 64; i++) {
        float av = ar[i];
#pragma unroll
        for (int o = 0; o < 64; o++) acc[o] = fmaf(av, Ut[i][o], acc[o]);
    }
    float* yr = g_y + (size_t)row * DD;
    float sc = 0.f;
#pragma unroll
    for (int o = 0; o < 64; o++) {
        float v = acc[o] > 0.f ? acc[o] : 0.f;
        yr[o] = v;
        sc = fmaf(v, ps[o], sc);
    }
    g_score[row] = sc * pinv;
}

// layer-3 full concat GEMM + fused score
__global__ void __launch_bounds__(128)
k_gemmcat(const float* __restrict__ U, const float* __restrict__ p, int n) {
    __shared__ float Ut[128][64];
    __shared__ float ps[64];
    __shared__ float pinv;
    for (int t = threadIdx.x; t < 128 * 64; t += blockDim.x) {
        int o = t >> 7, i = t & 127;
        Ut[i][o] = U[t];
    }
    if (threadIdx.x < 64) ps[threadIdx.x] = p[threadIdx.x];
    __syncthreads();
    if (threadIdx.x == 0) {
        float s = 0.f;
        for (int i = 0; i < 64; i++) s += ps[i] * ps[i];
        pinv = 1.0f / sqrtf(s);
    }
    __syncthreads();
    int row = blockIdx.x * blockDim.x + threadIdx.x;
    if (row >= n) return;
    const float* ar = g_aggr + (size_t)row * DD;
    const float* xr = g_x   + (size_t)row * DD;
    float acc[64];
#pragma unroll
    for (int o = 0; o < 64; o++) acc[o] = 0.f;
#pragma unroll 4
    for (int i = 0; i < 64; i++) {
        float av = ar[i];
#pragma unroll
        for (int o = 0; o < 64; o++) acc[o] = fmaf(av, Ut[i][o], acc[o]);
    }
#pragma unroll 4
    for (int i = 0; i < 64; i++) {
        float xv = xr[i];
#pragma unroll
        for (int o = 0; o < 64; o++) acc[o] = fmaf(xv, Ut[64 + i][o], acc[o]);
    }
    float* yr = g_y + (size_t)row * DD;
    float sc = 0.f;
#pragma unroll
    for (int o = 0; o < 64; o++) {
        float v = acc[o] > 0.f ? acc[o] : 0.f;
        yr[o] = v;
        sc = fmaf(v, ps[o], sc);
    }
    g_score[row] = sc * pinv;
}

// ---------------- readouts --------------------------------------------------------

// layer-1 readout via per-combo counting (x rows are LUT rows)
__global__ void k_readout1c() {
    __shared__ int cnt[64];
    int b = blockIdx.x, t = threadIdx.x;   // 256 threads
    if (t < 64) cnt[t] = 0;
    __syncthreads();
    for (int j = t; j < K1; j += 256)
        atomicAdd(&cnt[g_combo2[b * K1 + j]], 1);
    __syncthreads();
    if (t < 64) {
        float mx = NEG_INF, sm = 0.f;
        for (int c = 0; c < 64; c++) {
            int n = cnt[c];
            if (n > 0) {
                float v = g_x2lut[c * 64 + t];
                mx = fmaxf(mx, v);
                sm = fmaf((float)n, v, sm);
            }
        }
        g_h[b * 128 + t]      += mx;
        g_h[b * 128 + 64 + t] += sm / (float)K1;
    }
}

// layer-2 -> layer-3: gather x (materialized) + fused readout
__global__ void k_gatherread2() {
    __shared__ float smx[4][64], ssm[4][64];
    int b = blockIdx.x;
    int d = threadIdx.x & 63, r = threadIdx.x >> 6;
    float mx = NEG_INF, sm = 0.f;
    for (int j = r; j < K2; j += 4) {
        int nw = b * K2 + j;
        float v = g_y[(size_t)g_selold[nw] * DD + d] * g_selscale[nw];
        g_x[(size_t)nw * DD + d] = v;
        mx = fmaxf(mx, v);
        sm += v;
    }
    smx[r][d] = mx; ssm[r][d] = sm;
    __syncthreads();
    if (r == 0) {
#pragma unroll
        for (int i = 1; i < 4; i++) {
            mx = fmaxf(mx, smx[i][d]);
            sm += ssm[i][d];
        }
        g_h[b * 128 + d]      += mx;
        g_h[b * 128 + 64 + d] += sm / (float)K2;
    }
}

// final: gather (registers only) + fused readout
__global__ void k_gatherread3() {
    __shared__ float smx[4][64], ssm[4][64];
    int b = blockIdx.x;
    int d = threadIdx.x & 63, r = threadIdx.x >> 6;
    float mx = NEG_INF, sm = 0.f;
    for (int j = r; j < K3; j += 4) {
        int nw = b * K3 + j;
        float v = g_y[(size_t)g_selold[nw] * DD + d] * g_selscale[nw];
        mx = fmaxf(mx, v);
        sm += v;
    }
    smx[r][d] = mx; ssm[r][d] = sm;
    __syncthreads();
    if (r == 0) {
#pragma unroll
        for (int i = 1; i < 4; i++) {
            mx = fmaxf(mx, smx[i][d]);
            sm += ssm[i][d];
        }
        g_h[b * 128 + d]      += mx;
        g_h[b * 128 + 64 + d] += sm / (float)K3;
    }
}

// ---------------- head ------------------------------------------------------------

__global__ void k_mlp(const float* __restrict__ l1W, const float* __restrict__ l1b,
                      const float* __restrict__ l2W, const float* __restrict__ l2b,
                      const float* __restrict__ l3W, const float* __restrict__ l3b,
                      float* __restrict__ out, int out_size) {
    int b = blockIdx.x;
    int o = threadIdx.x;   // 64
    __shared__ float h[128], s1[64], s2[64];
    h[o]      = g_h[b * 128 + o];
    h[o + 64] = g_h[b * 128 + 64 + o];
    __syncthreads();
    float a = l1b[o];
#pragma unroll 8
    for (int i = 0; i < 128; i++) a = fmaf(h[i], l1W[o * 128 + i], a);
    s1[o] = fmaxf(a, 0.f);
    __syncthreads();
    a = l2b[o];
#pragma unroll 8
    for (int i = 0; i < 64; i++) a = fmaf(s1[i], l2W[o * 64 + i], a);
    s2[o] = fmaxf(a, 0.f);
    __syncthreads();
    a = l3b[o];
#pragma unroll 8
    for (int i = 0; i < 64; i++) a = fmaf(s2[i], l3W[o * 64 + i], a);
    out[b * 64 + o] = 1.f / (1.f + expf(-a));
    // fused batch vector
    for (int i = o; i < K3; i += 64) {
        int pos = 8192 + b * K3 + i;
        if (pos < out_size) out[pos] = (float)b;
    }
}

// ---------------- host orchestration ----------------------------------------------

extern "C" void kernel_launch(void* const* d_in, const int* in_sizes, int n_in,
                              void* d_out, int out_size) {
    const int*   x_ids = (const int*)d_in[0];
    const int*   eidx  = (const int*)d_in[1];
    const float* emb   = (const float*)d_in[2];
    const float* W1 = (const float*)d_in[3];
    const float* b1 = (const float*)d_in[4];
    const float* U1 = (const float*)d_in[5];
    const float* p1 = (const float*)d_in[6];
    const float* W2 = (const float*)d_in[7];
    const float* b2 = (const float*)d_in[8];
    const float* U2 = (const float*)d_in[9];
    const float* p2 = (const float*)d_in[10];
    const float* W3 = (const float*)d_in[11];
    const float* b3 = (const float*)d_in[12];
    const float* U3 = (const float*)d_in[13];
    const float* p3 = (const float*)d_in[14];
    const float* l1W = (const float*)d_in[15];
    const float* l1b = (const float*)d_in[16];
    const float* l2W = (const float*)d_in[17];
    const float* l2b = (const float*)d_in[18];
    const float* l3W = (const float*)d_in[19];
    const float* l3b = (const float*)d_in[20];
    float* out = (float*)d_out;

    const int eb = ETOT / 256;
    const int n2 = BGR * K1;   // 104960
    const int n3 = BGR * K2;   // 83968

    // init + LUTs + layer-1
    k_zero_init<<<(NTOT + 255) / 256, 256>>>();
    k_mask1<<<eb, 256>>>(eidx, eidx + ETOT, x_ids);
    k_lutA<<<1, 512>>>(emb, W1, b1, U1, p1);
    k_lutB<<<8, 512>>>(W2, b2, U2);
    k_topk1<<<BGR, 1024>>>(x_ids);
    k_readout1c<<<BGR, 256>>>();
    k_remap1<<<eb, 256>>>(eidx, eidx + ETOT);

    // layer-2
    k_aggr2<<<(n2 * 32 + 255) / 256, 256>>>(n2);
    k_gemmcat2<<<(n2 + 127) / 128, 128>>>(U2, p2, n2);
    k_topk<<<BGR, 1024>>>(K1, K2, 1);
    k_gatherread2<<<BGR, 256>>>();
    k_remap2<<<eb, 256>>>();
    k_scan<<<BGR, 1024>>>(K2);
    k_fill<<<eb, 256>>>();

    // layer-3
    k_gemm64<<<(n3 + 127) / 128, 128>>>(W3, b3, n3);
    k_aggr3<<<(n3 * 32 + 255) / 256, 256>>>(n3);
    k_gemmcat<<<(n3 + 127) / 128, 128>>>(U3, p3, n3);
    k_topk<<<BGR, 1024>>>(K2, K3, 0);
    k_gatherread3<<<BGR, 256>>>();

    // head (+ fused batch vector)
    k_mlp<<<BGR, 64>>>(l1W, l1b, l2W, l2b, l3W, l3b, out, out_size);
}

// round 6
// speedup vs baseline: 1.2049x; 1.2049x over previous
#include <cuda_runtime.h>
#include <math.h>

// Problem constants
#define BGR   128
#define N0    1024
#define NTOT  131072
#define ETOT  2097152
#define EPG   16384
#define DD    64
#define K1    820
#define K2    656
#define K3    525

#define NEG_INF __int_as_float(0xff800000)

// ---------------- scratch ---------------------------------------------------
__device__ float g_x[NTOT * DD];      // layer-3 input features
__device__ float g_y[NTOT * DD];      // sage output (layers 2,3)
__device__ float g_msg[NTOT * DD];    // layer-3 messages
__device__ float g_aggr[NTOT * DD];
__device__ float g_score[NTOT];
__device__ int   g_selold[NTOT];
__device__ float g_selscale[NTOT];
__device__ int   g_inv[NTOT];
__device__ int   g_esrc[2][ETOT];
__device__ int   g_edst[2][ETOT];
__device__ unsigned char g_emask[2][ETOT];
__device__ float g_h[BGR * 2 * DD];
// CSR scratch (layer 3)
__device__ int   g_deg[NTOT];
__device__ int   g_headp[NTOT];
__device__ int   g_cur[NTOT];
__device__ int   g_csr[ETOT];
// combo / LUT scratch (layers 1-2)
__device__ int   g_mask1[NTOT];
__device__ int   g_combo2[NTOT];
__device__ unsigned long long g_pres2[NTOT];
__device__ float g_sc1lut[64];
__device__ float g_x2lut[64 * 64];
__device__ float g_msg2lut[64 * 64];
__device__ float g_x2part[64 * 64];

// ---------------- helpers ----------------------------------------------------

__device__ __forceinline__ unsigned long long packkey(float s, int idx) {
    unsigned u = __float_as_uint(s);
    u = (u & 0x80000000u) ? ~u : (u | 0x80000000u);   // monotone-increasing map
    unsigned hi = ~u;                                 // ascending hi = descending score
    return ((unsigned long long)hi << 32) | (unsigned)idx;
}

// ascending bitonic sort of 1024 register-resident u64 keys (one per thread)
__device__ __forceinline__ void bitonic1024(unsigned long long& key,
                                            unsigned long long* sk, int t) {
    for (int ksz = 2; ksz <= 1024; ksz <<= 1) {
        for (int j = ksz >> 1; j >= 32; j >>= 1) {
            sk[t] = key;
            __syncthreads();
            unsigned long long o = sk[t ^ j];
            bool keepmin = (((t & j) == 0) == ((t & ksz) == 0));
            key = (keepmin == (o < key)) ? o : key;
            __syncthreads();
        }
        int jmax = ((ksz >> 1) < 16) ? (ksz >> 1) : 16;
        for (int j = jmax; j >= 1; j >>= 1) {
            unsigned long long o = __shfl_xor_sync(0xffffffffu, key, j);
            bool keepmin = (((t & j) == 0) == ((t & ksz) == 0));
            key = (keepmin == (o < key)) ? o : key;
        }
    }
}

// ---------------- init --------------------------------------------------------

__global__ void k_zero_init() {
    int i = blockIdx.x * blockDim.x + threadIdx.x;
    if (i < NTOT) { g_mask1[i] = 0; g_deg[i] = 0; }
    if (i < BGR * 2 * DD) g_h[i] = 0.f;
}

// ---------------- layer-1/2 LUT machinery --------------------------------------

__global__ void k_mask1(const int* __restrict__ src,
                        const int* __restrict__ dst,
                        const int* __restrict__ x_ids) {
    int e = blockIdx.x * blockDim.x + threadIdx.x;
    if (e >= ETOT) return;
    atomicOr(&g_mask1[dst[e]], 1 << x_ids[src[e]]);
}

// Build all LUTs in one 256-thread block (R4-validated).
__global__ void __launch_bounds__(256)
k_lut1(const float* __restrict__ emb,
       const float* __restrict__ W1, const float* __restrict__ b1,
       const float* __restrict__ U1, const float* __restrict__ p1,
       const float* __restrict__ W2, const float* __restrict__ b2,
       const float* __restrict__ U2) {
    __shared__ float s_emb[4][64], s_m1[4][64], s_amax[16][64];
    __shared__ float s_y1[64][64], s_x2[64][64];
    __shared__ float s_scale[64];
    __shared__ float s_pinv;
    int t = threadIdx.x;
    s_emb[t >> 6][t & 63] = emb[t];
    if (t == 0) {
        float s = 0.f;
        for (int i = 0; i < 64; i++) s += p1[i] * p1[i];
        s_pinv = 1.0f / sqrtf(s);
    }
    __syncthreads();
    {
        int id = t >> 6, o = t & 63;
        float a = b1[o];
        for (int i = 0; i < 64; i++) a = fmaf(s_emb[id][i], W1[o * 64 + i], a);
        s_m1[id][o] = a > 0.f ? a : 0.f;
    }
    __syncthreads();
    for (int u = t; u < 16 * 64; u += 256) {
        int mask = u >> 6, o = u & 63;
        float v = NEG_INF;
        for (int id = 0; id < 4; id++)
            if ((mask >> id) & 1) v = fmaxf(v, s_m1[id][o]);
        if (mask == 0) v = 0.f;
        s_amax[mask][o] = v;
    }
    __syncthreads();
    for (int u = t; u < 64 * 64; u += 256) {
        int c = u >> 6, o = u & 63;
        int id = c >> 4, mask = c & 15;
        float a = 0.f;
        for (int i = 0; i < 64; i++) a = fmaf(s_amax[mask][i], U1[o * 128 + i], a);
        for (int i = 0; i < 64; i++) a = fmaf(s_emb[id][i], U1[o * 128 + 64 + i], a);
        s_y1[c][o] = a > 0.f ? a : 0.f;
    }
    __syncthreads();
    if (t < 64) {
        float s = 0.f;
        for (int i = 0; i < 64; i++) s = fmaf(s_y1[t][i], p1[i], s);
        s *= s_pinv;
        g_sc1lut[t] = s;
        s_scale[t]  = tanhf(s);
    }
    __syncthreads();
    for (int u = t; u < 64 * 64; u += 256) {
        int c = u >> 6, d = u & 63;
        float v = s_y1[c][d] * s_scale[c];
        s_x2[c][d] = v;
        g_x2lut[u] = v;
    }
    __syncthreads();
    for (int u = t; u < 64 * 64; u += 256) {
        int c = u >> 6, o = u & 63;
        float a = b2[o];
        for (int i = 0; i < 64; i++) a = fmaf(s_x2[c][i], W2[o * 64 + i], a);
        g_msg2lut[u] = a > 0.f ? a : 0.f;
        float x = 0.f;
        for (int i = 0; i < 64; i++) x = fmaf(s_x2[c][i], U2[o * 128 + 64 + i], x);
        g_x2part[u] = x;
    }
}

// ---------------- topk kernels --------------------------------------------------

// layer-1 topk: fused combo+score, seeds layer-2 combo/presence
__global__ void __launch_bounds__(1024)
k_topk1(const int* __restrict__ x_ids) {
    __shared__ unsigned long long sk[1024];
    __shared__ unsigned char scb[1024];
    int b = blockIdx.x, t = threadIdx.x;
    int node = b * 1024 + t;
    int id = x_ids[node];
    int c = id * 16 + (g_mask1[node] | (1 << id));
    scb[t] = (unsigned char)c;
    unsigned long long key = packkey(g_sc1lut[c], t);
    g_inv[node] = -1;
    __syncthreads();
    bitonic1024(key, sk, t);
    if (t < K1) {
        int idx = (int)(key & 0xffffffffu);
        int old = b * 1024 + idx;
        int nw  = b * K1 + t;
        g_inv[old]   = nw;
        int cc = scb[idx];
        g_combo2[nw] = cc;
        g_pres2[nw]  = 1ull << cc;
    }
}

// generic topk over g_score
__global__ void __launch_bounds__(1024)
k_topk(int n_per, int k, int write_inv) {
    __shared__ unsigned long long sk[1024];
    int b = blockIdx.x, t = threadIdx.x;
    unsigned long long key = 0xFFFFFFFFFFFFFFFFull;
    if (t < n_per) {
        key = packkey(g_score[b * n_per + t], t);
        if (write_inv) g_inv[b * n_per + t] = -1;
    }
    __syncthreads();
    bitonic1024(key, sk, t);
    if (t < k) {
        int idx = (int)(key & 0xffffffffu);
        int old = b * n_per + idx;
        int nw  = b * k + t;
        g_selold[nw]   = old;
        g_selscale[nw] = tanhf(g_score[old]);
        if (write_inv) g_inv[old] = nw;
    }
}

// ---------------- edge passes (R4 banked style) ---------------------------------

// raw edges -> bank 0
__global__ void k_remap1(const int* __restrict__ src,
                         const int* __restrict__ dst) {
    int e = blockIdx.x * blockDim.x + threadIdx.x;
    if (e >= ETOT) return;
    int ns = g_inv[src[e]];
    int nd = g_inv[dst[e]];
    bool nm = (ns >= 0) && (nd >= 0);
    g_esrc[0][e]  = nm ? ns : 0;
    g_edst[0][e]  = nm ? nd : 0;
    g_emask[0][e] = nm ? 1 : 0;
}

// layer-2 presence OR over bank-0 edges
__global__ void k_mask2() {
    int e = blockIdx.x * blockDim.x + threadIdx.x;
    if (e >= ETOT) return;
    if (!g_emask[0][e]) return;
    int s = g_esrc[0][e], d = g_edst[0][e];
    atomicOr(&g_pres2[d], 1ull << g_combo2[s]);
}

// bank0 -> bank1, fused degree count
__global__ void k_remap2() {
    int e = blockIdx.x * blockDim.x + threadIdx.x;
    if (e >= ETOT) return;
    bool m = g_emask[0][e] != 0;
    int ns = 0, nd = 0; bool nm = false;
    if (m) {
        ns = g_inv[g_esrc[0][e]];
        nd = g_inv[g_edst[0][e]];
        nm = (ns >= 0) && (nd >= 0);
    }
    g_esrc[1][e]  = nm ? ns : 0;
    g_edst[1][e]  = nm ? nd : 0;
    g_emask[1][e] = nm ? 1 : 0;
    if (nm) atomicAdd(&g_deg[nd], 1);
}

__global__ void __launch_bounds__(1024)
k_scan(int n_per) {
    __shared__ int s[1024];
    int g = blockIdx.x, t = threadIdx.x;
    int v = (t < n_per) ? g_deg[g * n_per + t] : 0;
    s[t] = v;
    __syncthreads();
    for (int off = 1; off < 1024; off <<= 1) {
        int u = (t >= off) ? s[t - off] : 0;
        __syncthreads();
        s[t] += u;
        __syncthreads();
    }
    if (t < n_per) {
        int h = g * EPG + (s[t] - v);
        g_headp[g * n_per + t] = h;
        g_cur[g * n_per + t]   = h;
    }
}

__global__ void k_fill(int n_per) {
    int e = blockIdx.x * blockDim.x + threadIdx.x;
    if (e >= ETOT) return;
    if (!g_emask[1][e]) return;
    int s = g_esrc[1][e], d = g_edst[1][e];
    int gbase = (s / n_per) * n_per;
    int pos = atomicAdd(&g_cur[d], 1);
    g_csr[pos] = s - gbase;
}

// ---------------- aggregation ---------------------------------------------------

// layer-2: max over present msg2 LUT rows (L1-hot 16KB table)
__global__ void k_aggr2(int n) {
    int w = (blockIdx.x * blockDim.x + threadIdx.x) >> 5;
    int lane = threadIdx.x & 31;
    if (w >= n) return;
    unsigned long long m = g_pres2[w];
    float m0 = NEG_INF, m1 = NEG_INF;
    while (m) {
        int c = __ffsll(m) - 1;
        m &= m - 1;
        const float* r = g_msg2lut + c * 64;
        m0 = fmaxf(m0, __ldg(r + lane));
        m1 = fmaxf(m1, __ldg(r + lane + 32));
    }
    float* ar = g_aggr + (size_t)w * DD;
    ar[lane]      = m0;
    ar[lane + 32] = m1;
}

// layer-3: CSR gather-max with self-loop init
__global__ void k_aggr3(int n, int n_per) {
    int w = (blockIdx.x * blockDim.x + threadIdx.x) >> 5;
    int lane = threadIdx.x & 31;
    if (w >= n) return;
    int gbase = (w / n_per) * n_per;
    const float* mrow = g_msg + (size_t)w * DD;
    float m0 = mrow[lane];
    float m1 = mrow[lane + 32];
    int e   = g_headp[w];
    int end = g_cur[w];
    const float* mg = g_msg + (size_t)gbase * DD;
    for (; e + 4 <= end; e += 4) {
        int s0 = __ldg(&g_csr[e]);
        int s1 = __ldg(&g_csr[e + 1]);
        int s2 = __ldg(&g_csr[e + 2]);
        int s3 = __ldg(&g_csr[e + 3]);
        const float* r0 = mg + (size_t)s0 * DD;
        const float* r1 = mg + (size_t)s1 * DD;
        const float* r2 = mg + (size_t)s2 * DD;
        const float* r3 = mg + (size_t)s3 * DD;
        float a0 = r0[lane], b0 = r0[lane + 32];
        float a1 = r1[lane], b1 = r1[lane + 32];
        float a2 = r2[lane], b2 = r2[lane + 32];
        float a3 = r3[lane], b3 = r3[lane + 32];
        m0 = fmaxf(fmaxf(fmaxf(m0, a0), fmaxf(a1, a2)), a3);
        m1 = fmaxf(fmaxf(fmaxf(m1, b0), fmaxf(b1, b2)), b3);
    }
    for (; e < end; e++) {
        int s0 = __ldg(&g_csr[e]);
        const float* r0 = mg + (size_t)s0 * DD;
        m0 = fmaxf(m0, r0[lane]);
        m1 = fmaxf(m1, r0[lane + 32]);
    }
    float* ar = g_aggr + (size_t)w * DD;
    ar[lane]      = m0;
    ar[lane + 32] = m1;
}

// ---------------- GEMMs ----------------------------------------------------------

__global__ void __launch_bounds__(128)
k_gemm64(const float* __restrict__ W, const float* __restrict__ bias, int n) {
    __shared__ float Wt[64][64];
    for (int t = threadIdx.x; t < 64 * 64; t += blockDim.x) {
        int o = t >> 6, i = t & 63;
        Wt[i][o] = W[t];
    }
    __syncthreads();
    int row = blockIdx.x * blockDim.x + threadIdx.x;
    if (row >= n) return;
    const float* xr = g_x + (size_t)row * DD;
    float acc[64];
#pragma unroll
    for (int o = 0; o < 64; o++) acc[o] = bias[o];
#pragma unroll 8
    for (int i = 0; i < 64; i++) {
        float xv = xr[i];
#pragma unroll
        for (int o = 0; o < 64; o++) acc[o] = fmaf(xv, Wt[i][o], acc[o]);
    }
    float* m = g_msg + (size_t)row * DD;
#pragma unroll
    for (int o = 0; o < 64; o++) m[o] = acc[o] > 0.f ? acc[o] : 0.f;
}

// layer-2: y = relu(aggr @ Ua^T + x2part[combo]); fused score
__global__ void __launch_bounds__(128)
k_gemmcat2(const float* __restrict__ U, const float* __restrict__ p, int n) {
    __shared__ float Ut[64][64];
    __shared__ float x2p[64][65];
    __shared__ float ps[64];
    __shared__ float pinv;
    for (int t = threadIdx.x; t < 64 * 64; t += blockDim.x) {
        int o = t >> 6, i = t & 63;
        Ut[i][o]            = U[o * 128 + i];
        x2p[t >> 6][t & 63] = g_x2part[t];
    }
    if (threadIdx.x < 64) ps[threadIdx.x] = p[threadIdx.x];
    __syncthreads();
    if (threadIdx.x == 0) {
        float s = 0.f;
        for (int i = 0; i < 64; i++) s += ps[i] * ps[i];
        pinv = 1.0f / sqrtf(s);
    }
    __syncthreads();
    int row = blockIdx.x * blockDim.x + threadIdx.x;
    if (row >= n) return;
    int c = g_combo2[row];
    const float* ar = g_aggr + (size_t)row * DD;
    float acc[64];
#pragma unroll
    for (int o = 0; o < 64; o++) acc[o] = x2p[c][o];
#pragma unroll 4
    for (int i = 0; i < 64; i++) {
        float av = ar[i];
#pragma unroll
        for (int o = 0; o < 64; o++) acc[o] = fmaf(av, Ut[i][o], acc[o]);
    }
    float* yr = g_y + (size_t)row * DD;
    float sc = 0.f;
#pragma unroll
    for (int o = 0; o < 64; o++) {
        float v = acc[o] > 0.f ? acc[o] : 0.f;
        yr[o] = v;
        sc = fmaf(v, ps[o], sc);
    }
    g_score[row] = sc * pinv;
}

// layer-3 full concat GEMM + fused score
__global__ void __launch_bounds__(128)
k_gemmcat(const float* __restrict__ U, const float* __restrict__ p, int n) {
    __shared__ float Ut[128][64];
    __shared__ float ps[64];
    __shared__ float pinv;
    for (int t = threadIdx.x; t < 128 * 64; t += blockDim.x) {
        int o = t >> 7, i = t & 127;
        Ut[i][o] = U[t];
    }
    if (threadIdx.x < 64) ps[threadIdx.x] = p[threadIdx.x];
    __syncthreads();
    if (threadIdx.x == 0) {
        float s = 0.f;
        for (int i = 0; i < 64; i++) s += ps[i] * ps[i];
        pinv = 1.0f / sqrtf(s);
    }
    __syncthreads();
    int row = blockIdx.x * blockDim.x + threadIdx.x;
    if (row >= n) return;
    const float* ar = g_aggr + (size_t)row * DD;
    const float* xr = g_x   + (size_t)row * DD;
    float acc[64];
#pragma unroll
    for (int o = 0; o < 64; o++) acc[o] = 0.f;
#pragma unroll 4
    for (int i = 0; i < 64; i++) {
        float av = ar[i];
#pragma unroll
        for (int o = 0; o < 64; o++) acc[o] = fmaf(av, Ut[i][o], acc[o]);
    }
#pragma unroll 4
    for (int i = 0; i < 64; i++) {
        float xv = xr[i];
#pragma unroll
        for (int o = 0; o < 64; o++) acc[o] = fmaf(xv, Ut[64 + i][o], acc[o]);
    }
    float* yr = g_y + (size_t)row * DD;
    float sc = 0.f;
#pragma unroll
    for (int o = 0; o < 64; o++) {
        float v = acc[o] > 0.f ? acc[o] : 0.f;
        yr[o] = v;
        sc = fmaf(v, ps[o], sc);
    }
    g_score[row] = sc * pinv;
}

// ---------------- gathers & readouts -----------------------------------------------

// flat gather: x_new[j] = y[sel[j]] * scale[j]
__global__ void k_gather(int nk) {
    int idx = blockIdx.x * blockDim.x + threadIdx.x;
    if (idx >= nk * DD) return;
    int j = idx >> 6, d = idx & 63;
    g_x[idx] = g_y[(size_t)g_selold[j] * DD + d] * g_selscale[j];
}

// layer-1 readout via per-combo counting (x rows are LUT rows)
__global__ void k_readout1c() {
    __shared__ int cnt[64];
    int b = blockIdx.x, t = threadIdx.x;   // 256 threads
    if (t < 64) cnt[t] = 0;
    __syncthreads();
    for (int j = t; j < K1; j += 256)
        atomicAdd(&cnt[g_combo2[b * K1 + j]], 1);
    __syncthreads();
    if (t < 64) {
        float mx = NEG_INF, sm = 0.f;
        for (int c = 0; c < 64; c++) {
            int n = cnt[c];
            if (n > 0) {
                float v = g_x2lut[c * 64 + t];
                mx = fmaxf(mx, v);
                sm = fmaf((float)n, v, sm);
            }
        }
        g_h[b * 128 + t]      += mx;
        g_h[b * 128 + 64 + t] += sm / (float)K1;
    }
}

// contiguous readout over g_x (layers 2,3)
__global__ void k_readout(int k) {
    __shared__ float smx[4][64], ssm[4][64];
    int b = blockIdx.x;
    int d = threadIdx.x & 63;
    int r = threadIdx.x >> 6;
    int per = (k + 3) / 4;
    int j0 = r * per;
    int j1 = min(k, j0 + per);
    float mx = NEG_INF, sm = 0.f;
    const float* base = g_x + (size_t)b * k * DD + d;
    for (int j = j0; j < j1; j++) {
        float v = base[(size_t)j * DD];
        mx = fmaxf(mx, v);
        sm += v;
    }
    smx[r][d] = mx; ssm[r][d] = sm;
    __syncthreads();
    if (r == 0) {
#pragma unroll
        for (int i = 1; i < 4; i++) {
            mx = fmaxf(mx, smx[i][d]);
            sm += ssm[i][d];
        }
        g_h[b * 128 + d]      += mx;
        g_h[b * 128 + 64 + d] += sm / (float)k;
    }
}

// ---------------- head ------------------------------------------------------------

__global__ void k_mlp(const float* __restrict__ l1W, const float* __restrict__ l1b,
                      const float* __restrict__ l2W, const float* __restrict__ l2b,
                      const float* __restrict__ l3W, const float* __restrict__ l3b,
                      float* __restrict__ out, int out_size) {
    int b = blockIdx.x;
    int o = threadIdx.x;   // 64
    __shared__ float h[128], s1[64], s2[64];
    h[o]      = g_h[b * 128 + o];
    h[o + 64] = g_h[b * 128 + 64 + o];
    __syncthreads();
    float a = l1b[o];
#pragma unroll 8
    for (int i = 0; i < 128; i++) a = fmaf(h[i], l1W[o * 128 + i], a);
    s1[o] = fmaxf(a, 0.f);
    __syncthreads();
    a = l2b[o];
#pragma unroll 8
    for (int i = 0; i < 64; i++) a = fmaf(s1[i], l2W[o * 64 + i], a);
    s2[o] = fmaxf(a, 0.f);
    __syncthreads();
    a = l3b[o];
#pragma unroll 8
    for (int i = 0; i < 64; i++) a = fmaf(s2[i], l3W[o * 64 + i], a);
    out[b * 64 + o] = 1.f / (1.f + expf(-a));
    for (int i = o; i < K3; i += 64) {
        int pos = 8192 + b * K3 + i;
        if (pos < out_size) out[pos] = (float)b;
    }
}

// ---------------- host orchestration ----------------------------------------------

extern "C" void kernel_launch(void* const* d_in, const int* in_sizes, int n_in,
                              void* d_out, int out_size) {
    const int*   x_ids = (const int*)d_in[0];
    const int*   eidx  = (const int*)d_in[1];
    const float* emb   = (const float*)d_in[2];
    const float* W1 = (const float*)d_in[3];
    const float* b1 = (const float*)d_in[4];
    const float* U1 = (const float*)d_in[5];
    const float* p1 = (const float*)d_in[6];
    const float* W2 = (const float*)d_in[7];
    const float* b2 = (const float*)d_in[8];
    const float* U2 = (const float*)d_in[9];
    const float* p2 = (const float*)d_in[10];
    const float* W3 = (const float*)d_in[11];
    const float* b3 = (const float*)d_in[12];
    const float* U3 = (const float*)d_in[13];
    const float* p3 = (const float*)d_in[14];
    const float* l1W = (const float*)d_in[15];
    const float* l1b = (const float*)d_in[16];
    const float* l2W = (const float*)d_in[17];
    const float* l2b = (const float*)d_in[18];
    const float* l3W = (const float*)d_in[19];
    const float* l3b = (const float*)d_in[20];
    float* out = (float*)d_out;

    const int eb = ETOT / 256;
    const int n2 = BGR * K1;   // 104960
    const int n3 = BGR * K2;   // 83968

    // ---- layer 1 (combo LUT path) ----
    k_zero_init<<<(NTOT + 255) / 256, 256>>>();
    k_mask1<<<eb, 256>>>(eidx, eidx + ETOT, x_ids);
    k_lut1<<<1, 256>>>(emb, W1, b1, U1, p1, W2, b2, U2);
    k_topk1<<<BGR, 1024>>>(x_ids);
    k_readout1c<<<BGR, 256>>>();
    k_remap1<<<eb, 256>>>(eidx, eidx + ETOT);

    // ---- layer 2 (presence-mask LUT path) ----
    k_mask2<<<eb, 256>>>();
    k_aggr2<<<(n2 * 32 + 255) / 256, 256>>>(n2);
    k_gemmcat2<<<(n2 + 127) / 128, 128>>>(U2, p2, n2);
    k_topk<<<BGR, 1024>>>(K1, K2, 1);
    k_gather<<<(n3 * DD + 255) / 256, 256>>>(n3);
    k_remap2<<<eb, 256>>>();
    k_readout<<<BGR, 256>>>(K2);
    k_scan<<<BGR, 1024>>>(K2);
    k_fill<<<eb, 256>>>(K2);

    // ---- layer 3 (full path) ----
    k_gemm64<<<(n3 + 127) / 128, 128>>>(W3, b3, n3);
    k_aggr3<<<(n3 * 32 + 255) / 256, 256>>>(n3, K2);
    k_gemmcat<<<(n3 + 127) / 128, 128>>>(U3, p3, n3);
    k_topk<<<BGR, 1024>>>(K2, K3, 0);
    int nk3 = BGR * K3;
    k_gather<<<(nk3 * DD + 255) / 256, 256>>>(nk3);
    k_readout<<<BGR, 256>>>(K3);

    // ---- head (+ fused batch vector) ----
    k_mlp<<<BGR, 64>>>(l1W, l1b, l2W, l2b, l3W, l3b, out, out_size);
}